// round 4
// baseline (speedup 1.0000x reference)
#include <cuda_runtime.h>
#include <math.h>

#define NG    2048
#define HPIX  128
#define WPIX  128
#define NPIX  (HPIX*WPIX)
#define FOCAL 128.0f
#define NEARP 0.3f
#define EPSV  1e-4f

#define SEG   4
#define GPS   (NG/SEG)     // 512 gaussians per segment
#define RBLK  128          // render block = 128 threads = 128 pixels

// ---- scratch (device globals; no allocation allowed) ----
__device__ float  g_r[NG];
__device__ float4 g_A[NG];   // u, v, ia, ib  (unsorted)
__device__ float4 g_B[NG];   // ic, opa_eff, r, g
__device__ float  g_C[NG];   // b
__device__ float4 s_A[NG];   // sorted by depth r
__device__ float4 s_B[NG];
__device__ float  s_C[NG];
__device__ float4 g_part[SEG * NPIX]; // per-segment (cr,cg,cb,T)

__device__ __forceinline__ float sigmoidf(float x) {
    return 1.0f / (1.0f + expf(-x));
}

// ---------------- K1: per-gaussian preprocessing ----------------
__global__ void k_prep(const float* __restrict__ pos,
                       const float* __restrict__ rgb,
                       const float* __restrict__ opa,
                       const float* __restrict__ quat,
                       const float* __restrict__ scale,
                       const float* __restrict__ rot,
                       const float* __restrict__ tran)
{
    int i = blockIdx.x * blockDim.x + threadIdx.x;
    if (i >= NG) return;

    float R00=rot[0],R01=rot[1],R02=rot[2];
    float R10=rot[3],R11=rot[4],R12=rot[5];
    float R20=rot[6],R21=rot[7],R22=rot[8];

    float px = pos[3*i+0], py = pos[3*i+1], pz = pos[3*i+2];
    // pos @ rot.T + tran  ->  x_k = rot[k,:] . pos + tran[k]
    float x = R00*px + R01*py + R02*pz + tran[0];
    float y = R10*px + R11*py + R12*pz + tran[1];
    float z = R20*px + R21*py + R22*pz + tran[2];

    float r  = sqrtf(x*x + y*y + z*z);
    float iz = 1.0f / z;
    float u  = x * iz;
    float v  = y * iz;

    // J rows 0,1 only (row 2 never reaches the 2x2 cov)
    float J00 = iz,        J02 = -x * iz * iz;
    float J11 = iz,        J12 = -y * iz * iz;
    // JW = J @ rot ; rows 0,1
    float W00 = J00*R00 + J02*R20;
    float W01 = J00*R01 + J02*R21;
    float W02 = J00*R02 + J02*R22;
    float W10 = J11*R10 + J12*R20;
    float W11 = J11*R11 + J12*R21;
    float W12 = J11*R12 + J12*R22;

    // quaternion -> rotation
    float qw = quat[4*i+0], qx = quat[4*i+1], qy = quat[4*i+2], qz = quat[4*i+3];
    float qn = rsqrtf(qw*qw + qx*qx + qy*qy + qz*qz);
    qw*=qn; qx*=qn; qy*=qn; qz*=qn;
    float M00 = 1.f - 2.f*(qy*qy + qz*qz);
    float M01 = 2.f*(qx*qy - qw*qz);
    float M02 = 2.f*(qx*qz + qw*qy);
    float M10 = 2.f*(qx*qy + qw*qz);
    float M11 = 1.f - 2.f*(qx*qx + qz*qz);
    float M12 = 2.f*(qy*qz - qw*qx);
    float M20 = 2.f*(qx*qz - qw*qy);
    float M21 = 2.f*(qy*qz + qw*qx);
    float M22 = 1.f - 2.f*(qx*qx + qy*qy);

    float s0 = fabsf(scale[3*i+0]) + 1e-4f;
    float s1 = fabsf(scale[3*i+1]) + 1e-4f;
    float s2 = fabsf(scale[3*i+2]) + 1e-4f;

    // RS = M * diag(s); cov3d = RS RS^T (symmetric)
    float A00=M00*s0, A01=M01*s1, A02=M02*s2;
    float A10=M10*s0, A11=M11*s1, A12=M12*s2;
    float A20=M20*s0, A21=M21*s1, A22=M22*s2;
    float c00 = A00*A00 + A01*A01 + A02*A02;
    float c01 = A00*A10 + A01*A11 + A02*A12;
    float c02 = A00*A20 + A01*A21 + A02*A22;
    float c11 = A10*A10 + A11*A11 + A12*A12;
    float c12 = A10*A20 + A11*A21 + A12*A22;
    float c22 = A20*A20 + A21*A21 + A22*A22;

    // t0 = cov3d * W0^T, t1 = cov3d * W1^T
    float t00 = c00*W00 + c01*W01 + c02*W02;
    float t01 = c01*W00 + c11*W01 + c12*W02;
    float t02 = c02*W00 + c12*W01 + c22*W02;
    float t10 = c00*W10 + c01*W11 + c02*W12;
    float t11 = c01*W10 + c11*W11 + c12*W12;
    float t12 = c02*W10 + c12*W11 + c22*W12;

    float a = W00*t00 + W01*t01 + W02*t02 + EPSV;
    float b = W00*t10 + W01*t11 + W02*t12;
    float c = W10*t10 + W11*t11 + W12*t12 + EPSV;

    float det  = a*c - b*b;
    float idet = 1.0f / det;
    float ia =  c * idet;
    float ib = -b * idet;
    float ic =  a * idet;

    float rr = sigmoidf(rgb[3*i+0]);
    float rg = sigmoidf(rgb[3*i+1]);
    float rb = sigmoidf(rgb[3*i+2]);
    float op = sigmoidf(opa[i]);
    float opa_eff = (z > NEARP) ? op : 0.0f;

    g_r[i] = r;
    g_A[i] = make_float4(u, v, ia, ib);
    g_B[i] = make_float4(ic, opa_eff, rr, rg);
    g_C[i] = rb;
}

// ---------------- K2: stable rank-sort by depth + scatter ----------------
__global__ void k_sort()
{
    __shared__ float sr[NG];
    for (int j = threadIdx.x; j < NG; j += blockDim.x) sr[j] = g_r[j];
    __syncthreads();

    int i = blockIdx.x * blockDim.x + threadIdx.x;
    if (i >= NG) return;
    float ri = sr[i];
    int rank = 0;
#pragma unroll 8
    for (int j = 0; j < NG; j++) {
        float rj = sr[j];
        rank += (rj < ri) || (rj == ri && j < i);   // stable (matches argsort)
    }
    s_A[rank] = g_A[i];
    s_B[rank] = g_B[i];
    s_C[rank] = g_C[i];
}

// ---------------- K3: segmented front-to-back compositing ----------------
__global__ void __launch_bounds__(RBLK) k_render()
{
    int pix = blockIdx.x * RBLK + threadIdx.x;
    int seg = blockIdx.y;
    int col = pix & (WPIX-1);
    int row = pix >> 7;
    float pxf = ((float)col - WPIX*0.5f + 0.5f) / FOCAL;
    float pyf = ((float)row - HPIX*0.5f + 0.5f) / FOCAL;

    __shared__ float4 shA[RBLK];
    __shared__ float4 shB[RBLK];
    __shared__ float  shC[RBLK];

    float T = 1.0f, cr = 0.0f, cg = 0.0f, cb = 0.0f;
    int base = seg * GPS;

    for (int c0 = 0; c0 < GPS; c0 += RBLK) {
        int j = base + c0 + threadIdx.x;
        shA[threadIdx.x] = s_A[j];
        shB[threadIdx.x] = s_B[j];
        shC[threadIdx.x] = s_C[j];
        __syncthreads();

#pragma unroll 4
        for (int k = 0; k < RBLK; k++) {
            float4 A = shA[k];
            float4 B = shB[k];
            float dx = pxf - A.x;
            float dy = pyf - A.y;
            float q  = dx*(A.z*dx + 2.0f*A.w*dy) + B.x*dy*dy;
            float e  = __expf(-0.5f * q);
            float alpha = fminf(B.y * e, 0.99f);
            float w  = T * alpha;
            cr = fmaf(w, B.z,   cr);
            cg = fmaf(w, B.w,   cg);
            cb = fmaf(w, shC[k], cb);
            T -= w;                       // T *= (1 - alpha)
        }
        __syncthreads();
    }
    g_part[seg * NPIX + pix] = make_float4(cr, cg, cb, T);
}

// ---------------- K4: combine segments ----------------
__global__ void k_combine(float* __restrict__ out)
{
    int pix = blockIdx.x * blockDim.x + threadIdx.x;
    if (pix >= NPIX) return;
    float T = 1.0f, cr = 0.0f, cg = 0.0f, cb = 0.0f;
#pragma unroll
    for (int s = 0; s < SEG; s++) {
        float4 p = g_part[s * NPIX + pix];
        cr += T * p.x;
        cg += T * p.y;
        cb += T * p.z;
        T  *= p.w;
    }
    out[3*pix+0] = cr;
    out[3*pix+1] = cg;
    out[3*pix+2] = cb;
}

extern "C" void kernel_launch(void* const* d_in, const int* in_sizes, int n_in,
                              void* d_out, int out_size)
{
    const float* pos   = (const float*)d_in[0];
    const float* rgb   = (const float*)d_in[1];
    const float* opa   = (const float*)d_in[2];
    const float* quat  = (const float*)d_in[3];
    const float* scale = (const float*)d_in[4];
    const float* rot   = (const float*)d_in[5];
    const float* tran  = (const float*)d_in[6];
    float* out = (float*)d_out;

    k_prep<<<NG/128, 128>>>(pos, rgb, opa, quat, scale, rot, tran);
    k_sort<<<NG/128, 128>>>();
    k_render<<<dim3(NPIX/RBLK, SEG), RBLK>>>();
    k_combine<<<NPIX/128, 128>>>(out);
}

// round 5
// speedup vs baseline: 1.7502x; 1.7502x over previous
#include <cuda_runtime.h>
#include <math.h>

#define NG    2048
#define HPIX  128
#define WPIX  128
#define NPIX  (HPIX*WPIX)
#define FOCAL 128.0f
#define NEARP 0.3f
#define EPSV  1e-4f

#define SEG   4
#define GPS   (NG/SEG)     // 512 gaussians per segment
#define TPB   256          // render block = 256 threads = 16x16 tile
#define NTILE 64           // 8x8 tiles of 16x16 pixels

// ---- scratch (device globals; no allocation allowed) ----
__device__ float  g_r[NG];
__device__ float4 g_A[NG];   // u, v, ia, ib  (unsorted)
__device__ float4 g_B[NG];   // ic, opa_eff, r, g
__device__ float  g_C[NG];   // b
__device__ float2 g_H[NG];   // bbox half extents (hx, hy)
__device__ float4 s_A[NG];   // sorted by depth r
__device__ float4 s_B[NG];
__device__ float  s_C[NG];
__device__ float2 s_H[NG];
__device__ float4 g_part[SEG * NPIX]; // per-segment (cr,cg,cb,T)

__device__ __forceinline__ float sigmoidf(float x) {
    return 1.0f / (1.0f + expf(-x));
}

// ---------------- K1: per-gaussian preprocessing ----------------
__global__ void k_prep(const float* __restrict__ pos,
                       const float* __restrict__ rgb,
                       const float* __restrict__ opa,
                       const float* __restrict__ quat,
                       const float* __restrict__ scale,
                       const float* __restrict__ rot,
                       const float* __restrict__ tran)
{
    int i = blockIdx.x * blockDim.x + threadIdx.x;
    if (i >= NG) return;

    float R00=rot[0],R01=rot[1],R02=rot[2];
    float R10=rot[3],R11=rot[4],R12=rot[5];
    float R20=rot[6],R21=rot[7],R22=rot[8];

    float px = pos[3*i+0], py = pos[3*i+1], pz = pos[3*i+2];
    float x = R00*px + R01*py + R02*pz + tran[0];
    float y = R10*px + R11*py + R12*pz + tran[1];
    float z = R20*px + R21*py + R22*pz + tran[2];

    float r  = sqrtf(x*x + y*y + z*z);
    float iz = 1.0f / z;
    float u  = x * iz;
    float v  = y * iz;

    float J00 = iz,        J02 = -x * iz * iz;
    float J11 = iz,        J12 = -y * iz * iz;
    float W00 = J00*R00 + J02*R20;
    float W01 = J00*R01 + J02*R21;
    float W02 = J00*R02 + J02*R22;
    float W10 = J11*R10 + J12*R20;
    float W11 = J11*R11 + J12*R21;
    float W12 = J11*R12 + J12*R22;

    float qw = quat[4*i+0], qx = quat[4*i+1], qy = quat[4*i+2], qz = quat[4*i+3];
    float qn = rsqrtf(qw*qw + qx*qx + qy*qy + qz*qz);
    qw*=qn; qx*=qn; qy*=qn; qz*=qn;
    float M00 = 1.f - 2.f*(qy*qy + qz*qz);
    float M01 = 2.f*(qx*qy - qw*qz);
    float M02 = 2.f*(qx*qz + qw*qy);
    float M10 = 2.f*(qx*qy + qw*qz);
    float M11 = 1.f - 2.f*(qx*qx + qz*qz);
    float M12 = 2.f*(qy*qz - qw*qx);
    float M20 = 2.f*(qx*qz - qw*qy);
    float M21 = 2.f*(qy*qz + qw*qx);
    float M22 = 1.f - 2.f*(qx*qx + qy*qy);

    float s0 = fabsf(scale[3*i+0]) + 1e-4f;
    float s1 = fabsf(scale[3*i+1]) + 1e-4f;
    float s2 = fabsf(scale[3*i+2]) + 1e-4f;

    float A00=M00*s0, A01=M01*s1, A02=M02*s2;
    float A10=M10*s0, A11=M11*s1, A12=M12*s2;
    float A20=M20*s0, A21=M21*s1, A22=M22*s2;
    float c00 = A00*A00 + A01*A01 + A02*A02;
    float c01 = A00*A10 + A01*A11 + A02*A12;
    float c02 = A00*A20 + A01*A21 + A02*A22;
    float c11 = A10*A10 + A11*A11 + A12*A12;
    float c12 = A10*A20 + A11*A21 + A12*A22;
    float c22 = A20*A20 + A21*A21 + A22*A22;

    float t00 = c00*W00 + c01*W01 + c02*W02;
    float t01 = c01*W00 + c11*W01 + c12*W02;
    float t02 = c02*W00 + c12*W01 + c22*W02;
    float t10 = c00*W10 + c01*W11 + c02*W12;
    float t11 = c01*W10 + c11*W11 + c12*W12;
    float t12 = c02*W10 + c12*W11 + c22*W12;

    float a = W00*t00 + W01*t01 + W02*t02 + EPSV;
    float b = W00*t10 + W01*t11 + W02*t12;
    float c = W10*t10 + W11*t11 + W12*t12 + EPSV;

    float det  = a*c - b*b;
    float idet = 1.0f / det;
    float ia =  c * idet;
    float ib = -b * idet;
    float ic =  a * idet;

    float rr = sigmoidf(rgb[3*i+0]);
    float rg = sigmoidf(rgb[3*i+1]);
    float rb = sigmoidf(rgb[3*i+2]);
    float op = sigmoidf(opa[i]);
    float opa_eff = (z > NEARP) ? op : 0.0f;

    // conservative screen-space AABB: cull where alpha = opa*exp(-q/2) < ~1.5e-8
    float hx, hy;
    if (opa_eff < 1.5e-8f) {
        hx = -1e30f; hy = -1e30f;   // never overlaps any tile
    } else {
        float qc = 2.0f * (logf(opa_eff) + 18.0f);
        qc = fmaxf(qc, 0.0f);
        hx = sqrtf(qc * a);         // a = Sigma_xx (cov2d), extent of q<=qc ellipse in x
        hy = sqrtf(qc * c);
    }

    g_r[i] = r;
    g_A[i] = make_float4(u, v, ia, ib);
    g_B[i] = make_float4(ic, opa_eff, rr, rg);
    g_C[i] = rb;
    g_H[i] = make_float2(hx, hy);
}

// ---------------- K2: stable rank-sort by depth + scatter ----------------
__global__ void k_sort()
{
    __shared__ float sr[NG];
    for (int j = threadIdx.x; j < NG; j += blockDim.x) sr[j] = g_r[j];
    __syncthreads();

    int i = blockIdx.x * blockDim.x + threadIdx.x;
    if (i >= NG) return;
    float ri = sr[i];
    int rank = 0;
#pragma unroll 8
    for (int j = 0; j < NG; j++) {
        float rj = sr[j];
        rank += (rj < ri) || (rj == ri && j < i);   // stable (matches argsort)
    }
    s_A[rank] = g_A[i];
    s_B[rank] = g_B[i];
    s_C[rank] = g_C[i];
    s_H[rank] = g_H[i];
}

// ---------------- K3: tiled + culled front-to-back compositing ----------------
__global__ void __launch_bounds__(TPB) k_render()
{
    int tile = blockIdx.x;             // 0..63 (8x8 tiles of 16x16 px)
    int seg  = blockIdx.y;
    int tx = tile & 7, ty = tile >> 3;
    int lx = threadIdx.x & 15, ly = threadIdx.x >> 4;
    int col = tx * 16 + lx;
    int row = ty * 16 + ly;
    float pxf = ((float)col - 63.5f) / FOCAL;
    float pyf = ((float)row - 63.5f) / FOCAL;
    // tile pixel-center bounds
    float x0 = ((float)(tx * 16)      - 63.5f) / FOCAL;
    float x1 = ((float)(tx * 16 + 15) - 63.5f) / FOCAL;
    float y0 = ((float)(ty * 16)      - 63.5f) / FOCAL;
    float y1 = ((float)(ty * 16 + 15) - 63.5f) / FOCAL;

    __shared__ float4 cA[TPB];
    __shared__ float4 cB[TPB];
    __shared__ float  cC[TPB];
    __shared__ int    wcnt[TPB / 32];

    const int wid  = threadIdx.x >> 5;
    const int lane = threadIdx.x & 31;

    float T = 1.0f, cr = 0.0f, cg = 0.0f, cb = 0.0f;
    int base = seg * GPS;

    for (int c0 = 0; c0 < GPS; c0 += TPB) {
        int j = base + c0 + threadIdx.x;
        float4 A  = s_A[j];
        float4 B  = s_B[j];
        float  C  = s_C[j];
        float2 Hh = s_H[j];

        bool keep = (A.x + Hh.x >= x0) & (A.x - Hh.x <= x1) &
                    (A.y + Hh.y >= y0) & (A.y - Hh.y <= y1);

        unsigned m = __ballot_sync(0xffffffffu, keep);
        if (lane == 0) wcnt[wid] = __popc(m);
        __syncthreads();

        int off = 0, tot = 0;
#pragma unroll
        for (int w = 0; w < TPB / 32; w++) {
            if (w == wid) off = tot;
            tot += wcnt[w];
        }
        if (keep) {
            int idx = off + __popc(m & ((1u << lane) - 1u));
            cA[idx] = A;
            cB[idx] = B;
            cC[idx] = C;
        }
        __syncthreads();

        for (int k = 0; k < tot; k++) {
            float4 Ak = cA[k];
            float4 Bk = cB[k];
            float dx = pxf - Ak.x;
            float dy = pyf - Ak.y;
            float q  = dx * (Ak.z * dx + 2.0f * Ak.w * dy) + Bk.x * dy * dy;
            float e  = __expf(-0.5f * q);
            float alpha = fminf(Bk.y * e, 0.99f);
            float w  = T * alpha;
            cr = fmaf(w, Bk.z,  cr);
            cg = fmaf(w, Bk.w,  cg);
            cb = fmaf(w, cC[k], cb);
            T -= w;                       // T *= (1 - alpha)
        }
        __syncthreads();
    }
    int pix = row * WPIX + col;
    g_part[seg * NPIX + pix] = make_float4(cr, cg, cb, T);
}

// ---------------- K4: combine segments ----------------
__global__ void k_combine(float* __restrict__ out)
{
    int pix = blockIdx.x * blockDim.x + threadIdx.x;
    if (pix >= NPIX) return;
    float T = 1.0f, cr = 0.0f, cg = 0.0f, cb = 0.0f;
#pragma unroll
    for (int s = 0; s < SEG; s++) {
        float4 p = g_part[s * NPIX + pix];
        cr += T * p.x;
        cg += T * p.y;
        cb += T * p.z;
        T  *= p.w;
    }
    out[3*pix+0] = cr;
    out[3*pix+1] = cg;
    out[3*pix+2] = cb;
}

extern "C" void kernel_launch(void* const* d_in, const int* in_sizes, int n_in,
                              void* d_out, int out_size)
{
    const float* pos   = (const float*)d_in[0];
    const float* rgb   = (const float*)d_in[1];
    const float* opa   = (const float*)d_in[2];
    const float* quat  = (const float*)d_in[3];
    const float* scale = (const float*)d_in[4];
    const float* rot   = (const float*)d_in[5];
    const float* tran  = (const float*)d_in[6];
    float* out = (float*)d_out;

    k_prep<<<NG/128, 128>>>(pos, rgb, opa, quat, scale, rot, tran);
    k_sort<<<NG/128, 128>>>();
    k_render<<<dim3(NTILE, SEG), TPB>>>();
    k_combine<<<NPIX/128, 128>>>(out);
}